// round 13
// baseline (speedup 1.0000x reference)
#include <cuda_runtime.h>
#include <cuda_bf16.h>
#include <math.h>

// AdaptiveGraphGenerator: dim=128, B=1, N=1024.
// edge predictor is dead code (edge_probs = ones). adj = (1.0 > threshold).
// Real work: node encoder LN(x@W1+b1) -> GELU -> @W2+b2.
//
// R13: smem-staged weights + warp-broadcast GEMMs.
// grid=148 (1 block/SM), 1024 threads, 7 (or 6) rows/block padded to 8 slots.
// W1 staged fully into 128KB dynamic smem, GEMM1 warps = 4 colgroups x 8 rows
// (8 row-lanes broadcast-share each weight LDS.128). W2 re-staged into the
// same region during the GELU phase. Per-SM global weight traffic = 256KB
// (theoretical minimum); FFMA pipe becomes the binding resource.

#define DIM 128
#define HID 256
#define NROWS 1024
#define THREADS 1024
#define NBLOCKS 148
#define NFULL 136              // blocks with 7 rows; rest have 6
#define RSLOT 8
#define ADJ_VEC4 262144        // 1024*1024/4
#define ADJ_PER_BLK 1772       // ceil(262144/148)

// dynamic smem layout (float offsets)
#define OFF_W    0             // 32768 floats = 128KB (W1 then W2)
#define OFF_X    32768         // sx[128][9]  = 1152
#define OFF_SH   33920         // sh[256][9]  = 2304
#define OFF_SCR  36224         // 4096 (p1[2][8][256] then p2[4][8][128])
#define OFF_SUM  40320         // s_sum[32][2] = 64
#define OFF_SQ   40384         // s_sq[32][2]  = 64
#define SMEM_FLOATS 40448
#define SMEM_BYTES (SMEM_FLOATS * 4)   // 161792

__device__ __forceinline__ float gelu_exact(float v) {
    return 0.5f * v * (1.0f + erff(v * 0.70710678118654752f));
}

__global__ __launch_bounds__(THREADS, 1)
void fused_kernel(const float* __restrict__ x,
                  const float* __restrict__ W1,
                  const float* __restrict__ b1,
                  const float* __restrict__ ln_g,
                  const float* __restrict__ ln_b,
                  const float* __restrict__ W2,
                  const float* __restrict__ b2,
                  const float* __restrict__ thr,
                  float* __restrict__ adj_out,
                  float* __restrict__ node_out) {
    extern __shared__ float dsm[];
    float* Ws   = dsm + OFF_W;
    float* sx   = dsm + OFF_X;      // [k up to 128][9] padded
    float* sh   = dsm + OFF_SH;     // [k up to 256][9] padded
    float* scr  = dsm + OFF_SCR;
    float* ssum = dsm + OFF_SUM;    // [32][2]
    float* ssq  = dsm + OFF_SQ;     // [32][2]

    const int tid = threadIdx.x;    // 0..1023
    const int bid = blockIdx.x;
    const int nr   = (bid < NFULL) ? 7 : 6;
    const int row0 = (bid < NFULL) ? (7 * bid) : (7 * NFULL + 6 * (bid - NFULL));

    // ---- scalar prefetches ----
    const float tv    = __ldg(&thr[0]);
    const float bias1 = __ldg(&b1[tid & 255]);
    const float gg    = __ldg(&ln_g[tid & 255]);
    const float bb    = __ldg(&ln_b[tid & 255]);
    const float bias2 = __ldg(&b2[tid & (DIM - 1)]);

    // ---- stage W1 (128KB) into smem: 8 float4 per thread, coalesced ----
    {
        const float4* W1v = reinterpret_cast<const float4*>(W1);
        float4* Wv = reinterpret_cast<float4*>(Ws);
        #pragma unroll
        for (int j = 0; j < 8; j++)
            Wv[tid + j * 1024] = W1v[tid + j * 1024];
    }

    // ---- x tile: thread (r = tid>>7 slot 0-7, c = tid&127); dup last rows ----
    {
        const int r = tid >> 7;
        const int c = tid & (DIM - 1);
        const int re = (r < nr) ? r : (nr - 1);
        sx[c * 9 + r] = __ldg(&x[(size_t)(row0 + re) * DIM + c]);
    }

    // ---- adj fill: 1772-float4 slice, bounds-checked ----
    {
        const float v = (1.0f > tv) ? 1.0f : 0.0f;
        const float4 f4 = make_float4(v, v, v, v);
        float4* a4 = reinterpret_cast<float4*>(adj_out);
        const int base = bid * ADJ_PER_BLK;
        const int lim  = (base + ADJ_PER_BLK < ADJ_VEC4) ? base + ADJ_PER_BLK
                                                         : ADJ_VEC4;
        for (int i = base + tid; i < lim; i += THREADS)
            a4[i] = f4;
    }
    __syncthreads();

    // ---- GEMM1: warp w: ks = w>>4 (k half), cgq = w&15 (16 colgroups of 16).
    //      lane: c4 = 16*cgq + 4*(l>>3), row = l&7.
    //      Weight LDS.128 is 8-way broadcast across row-lanes. ----
    {
        const int w  = tid >> 5;
        const int l  = tid & 31;
        const int ks = w >> 4;               // 0..1
        const int cgq = w & 15;              // 0..15
        const int c4 = cgq * 16 + (l >> 3) * 4;
        const int row = l & 7;
        const float* wp = Ws + (size_t)(ks * 64) * HID + c4;
        const float* xp = sx + (ks * 64) * 9 + row;
        float4 acc = make_float4(0.f, 0.f, 0.f, 0.f);
        #pragma unroll 8
        for (int k = 0; k < 64; k++) {
            const float4 w4 = *reinterpret_cast<const float4*>(wp + (size_t)k * HID);
            const float xv = xp[k * 9];
            acc.x = fmaf(xv, w4.x, acc.x);
            acc.y = fmaf(xv, w4.y, acc.y);
            acc.z = fmaf(xv, w4.z, acc.z);
            acc.w = fmaf(xv, w4.w, acc.w);
        }
        // p1[ks][row][c4] at scr[(ks*8+row)*256 + c4]
        *reinterpret_cast<float4*>(scr + (ks * 8 + row) * 256 + c4) = acc;
    }
    __syncthreads();

    // ---- combine k-halves + LN partials: c = tid&255, rp = tid>>8 ->
    //      rows {2rp, 2rp+1} ----
    float v0, v1;
    const int rp = tid >> 8;                 // 0..3
    {
        const int c  = tid & 255;
        const int r0 = 2 * rp, r1 = 2 * rp + 1;
        v0 = scr[r0 * 256 + c] + scr[(8 + r0) * 256 + c] + bias1;
        v1 = scr[r1 * 256 + c] + scr[(8 + r1) * 256 + c] + bias1;
        const int w    = tid >> 5;
        const int lane = tid & 31;
        float s0 = v0, q0 = v0 * v0, s1 = v1, q1 = v1 * v1;
        #pragma unroll
        for (int o = 16; o > 0; o >>= 1) {
            s0 += __shfl_xor_sync(0xffffffffu, s0, o);
            q0 += __shfl_xor_sync(0xffffffffu, q0, o);
            s1 += __shfl_xor_sync(0xffffffffu, s1, o);
            q1 += __shfl_xor_sync(0xffffffffu, q1, o);
        }
        if (lane == 0) {
            ssum[w * 2 + 0] = s0;  ssq[w * 2 + 0] = q0;
            ssum[w * 2 + 1] = s1;  ssq[w * 2 + 1] = q1;
        }
    }
    __syncthreads();

    // ---- LN finalize + GELU -> sh; stage W2 into Ws concurrently ----
    {
        const int c = tid & 255;
        float s0 = 0.f, q0 = 0.f, s1 = 0.f, q1 = 0.f;
        #pragma unroll
        for (int j = 0; j < 8; j++) {
            const int wdx = (8 * rp + j) * 2;
            s0 += ssum[wdx];     q0 += ssq[wdx];
            s1 += ssum[wdx + 1]; q1 += ssq[wdx + 1];
        }
        const float m0 = s0 * (1.0f / HID);
        const float m1 = s1 * (1.0f / HID);
        const float rs0 = rsqrtf(q0 * (1.0f / HID) - m0 * m0 + 1e-5f);
        const float rs1 = rsqrtf(q1 * (1.0f / HID) - m1 * m1 + 1e-5f);
        sh[c * 9 + 2 * rp]     = gelu_exact((v0 - m0) * rs0 * gg + bb);
        sh[c * 9 + 2 * rp + 1] = gelu_exact((v1 - m1) * rs1 * gg + bb);

        // stage W2 (128KB) — Ws reads finished before the post-GEMM1 barrier
        const float4* W2v = reinterpret_cast<const float4*>(W2);
        float4* Wv = reinterpret_cast<float4*>(Ws);
        #pragma unroll
        for (int j = 0; j < 8; j++)
            Wv[tid + j * 1024] = W2v[tid + j * 1024];
    }
    __syncthreads();

    // ---- GEMM2: warp w: ks2 = w>>3 (4 k-quarters of 64), cgo = w&7
    //      (8 colgroups of 16). lane: c4 = 16*cgo + 4*(l>>3), row = l&7. ----
    {
        const int w   = tid >> 5;
        const int l   = tid & 31;
        const int ks2 = w >> 3;              // 0..3
        const int cgo = w & 7;               // 0..7
        const int c4 = cgo * 16 + (l >> 3) * 4;
        const int row = l & 7;
        const float* wp = Ws + (size_t)(ks2 * 64) * DIM + c4;
        const float* gp = sh + (ks2 * 64) * 9 + row;
        float4 acc = make_float4(0.f, 0.f, 0.f, 0.f);
        #pragma unroll 8
        for (int k = 0; k < 64; k++) {
            const float4 w4 = *reinterpret_cast<const float4*>(wp + (size_t)k * DIM);
            const float gv = gp[k * 9];
            acc.x = fmaf(gv, w4.x, acc.x);
            acc.y = fmaf(gv, w4.y, acc.y);
            acc.z = fmaf(gv, w4.z, acc.z);
            acc.w = fmaf(gv, w4.w, acc.w);
        }
        // p2[ks2][row][c4] at scr[(ks2*8+row)*128 + c4]
        *reinterpret_cast<float4*>(scr + (ks2 * 8 + row) * 128 + c4) = acc;
    }
    __syncthreads();

    // ---- combine GEMM2 k-quarters + store (r = tid>>7, c = tid&127) ----
    {
        const int r = tid >> 7;              // 0..7
        const int c = tid & (DIM - 1);
        float o = bias2;
        #pragma unroll
        for (int s = 0; s < 4; s++)
            o += scr[(s * 8 + r) * 128 + c];
        if (r < nr)
            node_out[(size_t)(row0 + r) * DIM + c] = o;
    }
}

extern "C" void kernel_launch(void* const* d_in, const int* in_sizes, int n_in,
                              void* d_out, int out_size) {
    const float* x    = (const float*)d_in[0];
    const float* W1   = (const float*)d_in[1];
    const float* b1   = (const float*)d_in[2];
    const float* ln_g = (const float*)d_in[3];
    const float* ln_b = (const float*)d_in[4];
    const float* W2   = (const float*)d_in[5];
    const float* b2   = (const float*)d_in[6];
    const float* thr  = (const float*)d_in[11];

    float* out = (float*)d_out;
    float* adj_out  = out;                      // [1,1024,1024,1]
    float* node_out = out + NROWS * NROWS;      // [1,1024,128]

    cudaFuncSetAttribute(fused_kernel,
                         cudaFuncAttributeMaxDynamicSharedMemorySize, SMEM_BYTES);
    fused_kernel<<<NBLOCKS, THREADS, SMEM_BYTES>>>(
        x, W1, b1, ln_g, ln_b, W2, b2, thr, adj_out, node_out);
}

// round 15
// speedup vs baseline: 1.3233x; 1.3233x over previous
#include <cuda_runtime.h>
#include <cuda_bf16.h>
#include <math.h>
#include <stdint.h>

// AdaptiveGraphGenerator: dim=128, B=1, N=1024.
// edge predictor is dead code (edge_probs = ones). adj = (1.0 > threshold).
// Real work: node encoder LN(x@W1+b1) -> GELU -> @W2+b2.
//
// R15 = R14 resubmit (prior round was an infra container failure; fragment
// maps re-audited against PTX ISA).
// tf32 tensor-core path (mma.sync.m16n8k8.row.col.f32.tf32.tf32.f32).
// 128 blocks x 512 threads x 8 rows (M=16 tile, rows 8-15 zero-pad -> A-frag
// a1=a3=0). Weights staged once into smem with frag-conflict-free padded
// strides (264/136 for B, 132/260 for A). 4 barriers. W2 staged during the
// LN-partial phase. tf32 via cvt.rna; fp32 accumulate.

#define DIM 128
#define HID 256
#define NROWS 1024
#define THREADS 512
#define NBLOCKS 128

// smem layout (float offsets)
#define OFF_WB   0        // W1 [128][264]=33792 fl, then W2 [256][136]=34816 fl
#define OFF_SX   34816    // sx [8][132] = 1056 fl  (tf32-rounded x)
#define OFF_SG   35872    // sg [8][260] = 2080 fl  (h, then tf32 gelu(h))
#define OFF_PSUM 37952    // [16][4]
#define OFF_PSQ  38016    // [16][4]
#define SMEM_FLOATS 38080
#define SMEM_BYTES (SMEM_FLOATS * 4)   // 152320

__device__ __forceinline__ float gelu_exact(float v) {
    return 0.5f * v * (1.0f + erff(v * 0.70710678118654752f));
}

__device__ __forceinline__ uint32_t f2tf(float f) {
    uint32_t u;
    asm("cvt.rna.tf32.f32 %0, %1;" : "=r"(u) : "f"(f));
    return u;
}

__device__ __forceinline__ void mma_tf32(float& d0, float& d1, float& d2, float& d3,
                                         uint32_t a0, uint32_t a1, uint32_t a2, uint32_t a3,
                                         uint32_t b0, uint32_t b1) {
    asm("mma.sync.aligned.m16n8k8.row.col.f32.tf32.tf32.f32 "
        "{%0,%1,%2,%3},{%4,%5,%6,%7},{%8,%9},{%0,%1,%2,%3};"
        : "+f"(d0), "+f"(d1), "+f"(d2), "+f"(d3)
        : "r"(a0), "r"(a1), "r"(a2), "r"(a3), "r"(b0), "r"(b1));
}

__global__ __launch_bounds__(THREADS, 1)
void fused_kernel(const float* __restrict__ x,
                  const float* __restrict__ W1,
                  const float* __restrict__ b1,
                  const float* __restrict__ ln_g,
                  const float* __restrict__ ln_b,
                  const float* __restrict__ W2,
                  const float* __restrict__ b2,
                  const float* __restrict__ thr,
                  float* __restrict__ adj_out,
                  float* __restrict__ node_out) {
    extern __shared__ float dsm[];
    float* Wb   = dsm + OFF_WB;
    float* sxf  = dsm + OFF_SX;      // [8][132]
    float* sgf  = dsm + OFF_SG;      // [8][260]
    float* psum = dsm + OFF_PSUM;    // [16][4]
    float* psq  = dsm + OFF_PSQ;     // [16][4]

    const int tid = threadIdx.x;     // 0..511
    const int bid = blockIdx.x;
    const int row0 = bid * 8;
    const int w   = tid >> 5;        // warp 0..15
    const int l   = tid & 31;
    const int gid = l >> 2;          // 0..7
    const int tg  = l & 3;           // 0..3

    const float bias1 = __ldg(&b1[tid & 255]);
    const float gg    = __ldg(&ln_g[tid & 255]);
    const float bb    = __ldg(&ln_b[tid & 255]);
    const float tv    = __ldg(&thr[0]);

    // ============ Phase 1: stage W1 (tf32), x tile (tf32), adj fill ============
    {
        // W1 [128][256] -> Wb[row*264 + col], tf32-rounded
        const float4* W1v = reinterpret_cast<const float4*>(W1);
        const int r  = tid >> 6;     // 0..7
        const int c4 = tid & 63;     // 0..63
        #pragma unroll
        for (int j = 0; j < 16; j++) {
            const int row = 8 * j + r;
            const float4 v = W1v[row * 64 + c4];
            float* dst = Wb + row * 264 + 4 * c4;
            dst[0] = __uint_as_float(f2tf(v.x));
            dst[1] = __uint_as_float(f2tf(v.y));
            dst[2] = __uint_as_float(f2tf(v.z));
            dst[3] = __uint_as_float(f2tf(v.w));
        }
        // x rows (8 x 128), tf32-rounded
        #pragma unroll
        for (int i = tid; i < 8 * DIM; i += THREADS) {
            const int r2 = i >> 7, c = i & 127;
            sxf[r2 * 132 + c] = __uint_as_float(f2tf(__ldg(&x[(size_t)(row0 + r2) * DIM + c])));
        }
        // adj fill: 2048 float4 per block
        const float av = (1.0f > tv) ? 1.0f : 0.0f;
        const float4 f4 = make_float4(av, av, av, av);
        float4* a4 = reinterpret_cast<float4*>(adj_out) + (size_t)bid * 2048;
        #pragma unroll
        for (int i = 0; i < 4; i++)
            a4[tid + i * THREADS] = f4;
    }
    __syncthreads();

    // ============ Phase 2: GEMM1 via mma (warp w -> n-tiles 16w, 16w+8) ============
    {
        const int n0a = 16 * w;
        const int n0b = n0a + 8;
        float dA0 = 0.f, dA1 = 0.f, dA2 = 0.f, dA3 = 0.f;
        float dB0 = 0.f, dB1 = 0.f, dB2 = 0.f, dB3 = 0.f;
        const float* ap = sxf + gid * 132 + tg;
        #pragma unroll
        for (int s = 0; s < 16; s++) {
            const int kb = 8 * s;
            const uint32_t a0 = __float_as_uint(ap[kb]);
            const uint32_t a2 = __float_as_uint(ap[kb + 4]);
            const float* bp = Wb + (size_t)(kb + tg) * 264;
            const uint32_t b0a = __float_as_uint(bp[n0a + gid]);
            const uint32_t b1a = __float_as_uint(bp[4 * 264 + n0a + gid]);
            const uint32_t b0b = __float_as_uint(bp[n0b + gid]);
            const uint32_t b1b = __float_as_uint(bp[4 * 264 + n0b + gid]);
            mma_tf32(dA0, dA1, dA2, dA3, a0, 0u, a2, 0u, b0a, b1a);
            mma_tf32(dB0, dB1, dB2, dB3, a0, 0u, a2, 0u, b0b, b1b);
        }
        // write h rows 0..7 (c0,c1); rows 8..15 (c2,c3) are pad -> discard
        float* hp = sgf + gid * 260;
        hp[n0a + 2 * tg]     = dA0;
        hp[n0a + 2 * tg + 1] = dA1;
        hp[n0b + 2 * tg]     = dB0;
        hp[n0b + 2 * tg + 1] = dB1;
    }
    __syncthreads();

    // ============ Phase 3: LN partials + stage W2 ============
    {
        const int c    = tid & 255;
        const int rset = tid >> 8;           // 0/1 -> rows 4rset..4rset+3
        float s[4], q[4];
        #pragma unroll
        for (int i = 0; i < 4; i++) {
            const float v = sgf[(4 * rset + i) * 260 + c] + bias1;
            s[i] = v; q[i] = v * v;
        }
        #pragma unroll
        for (int o = 16; o > 0; o >>= 1) {
            #pragma unroll
            for (int i = 0; i < 4; i++) {
                s[i] += __shfl_xor_sync(0xffffffffu, s[i], o);
                q[i] += __shfl_xor_sync(0xffffffffu, q[i], o);
            }
        }
        if (l == 0) {
            #pragma unroll
            for (int i = 0; i < 4; i++) { psum[w * 4 + i] = s[i]; psq[w * 4 + i] = q[i]; }
        }
        // stage W2 [256][128] -> Wb[row*136 + col], tf32 (W1 reads all done)
        const float4* W2v = reinterpret_cast<const float4*>(W2);
        const int r  = tid >> 5;     // 0..15
        const int c4 = tid & 31;     // 0..31
        #pragma unroll
        for (int j = 0; j < 16; j++) {
            const int row = 16 * j + r;
            const float4 v = W2v[row * 32 + c4];
            float* dst = Wb + row * 136 + 4 * c4;
            dst[0] = __uint_as_float(f2tf(v.x));
            dst[1] = __uint_as_float(f2tf(v.y));
            dst[2] = __uint_as_float(f2tf(v.z));
            dst[3] = __uint_as_float(f2tf(v.w));
        }
    }
    __syncthreads();

    // ============ Phase 4: LN finalize + GELU (tf32) in-place ============
    {
        const int c    = tid & 255;
        const int rset = tid >> 8;
        #pragma unroll
        for (int i = 0; i < 4; i++) {
            float s = 0.f, q = 0.f;
            #pragma unroll
            for (int ww = 0; ww < 8; ww++) {
                s += psum[(8 * rset + ww) * 4 + i];
                q += psq[(8 * rset + ww) * 4 + i];
            }
            const float m  = s * (1.0f / HID);
            const float rs = rsqrtf(q * (1.0f / HID) - m * m + 1e-5f);
            const int idx = (4 * rset + i) * 260 + c;
            const float v = sgf[idx] + bias1;
            const float g = gelu_exact((v - m) * rs * gg + bb);
            sgf[idx] = __uint_as_float(f2tf(g));
        }
    }
    __syncthreads();

    // ============ Phase 5: GEMM2 via mma (warp w -> n-tile n0 = 8w) ============
    {
        const int n0 = 8 * w;
        const float bo0 = __ldg(&b2[n0 + 2 * tg]);
        const float bo1 = __ldg(&b2[n0 + 2 * tg + 1]);
        float d0 = 0.f, d1 = 0.f, d2 = 0.f, d3 = 0.f;
        const float* ap = sgf + gid * 260 + tg;
        #pragma unroll
        for (int s = 0; s < 32; s++) {
            const int kb = 8 * s;
            const uint32_t a0 = __float_as_uint(ap[kb]);
            const uint32_t a2 = __float_as_uint(ap[kb + 4]);
            const float* bp = Wb + (size_t)(kb + tg) * 136;
            const uint32_t b0 = __float_as_uint(bp[n0 + gid]);
            const uint32_t b1r = __float_as_uint(bp[4 * 136 + n0 + gid]);
            mma_tf32(d0, d1, d2, d3, a0, 0u, a2, 0u, b0, b1r);
        }
        // rows 0..7 real (c0,c1); rows 8..15 pad -> discard
        node_out[(size_t)(row0 + gid) * DIM + n0 + 2 * tg]     = d0 + bo0;
        node_out[(size_t)(row0 + gid) * DIM + n0 + 2 * tg + 1] = d1 + bo1;
    }
}

extern "C" void kernel_launch(void* const* d_in, const int* in_sizes, int n_in,
                              void* d_out, int out_size) {
    const float* x    = (const float*)d_in[0];
    const float* W1   = (const float*)d_in[1];
    const float* b1   = (const float*)d_in[2];
    const float* ln_g = (const float*)d_in[3];
    const float* ln_b = (const float*)d_in[4];
    const float* W2   = (const float*)d_in[5];
    const float* b2   = (const float*)d_in[6];
    const float* thr  = (const float*)d_in[11];

    float* out = (float*)d_out;
    float* adj_out  = out;                      // [1,1024,1024,1]
    float* node_out = out + NROWS * NROWS;      // [1,1024,128]

    cudaFuncSetAttribute(fused_kernel,
                         cudaFuncAttributeMaxDynamicSharedMemorySize, SMEM_BYTES);
    fused_kernel<<<NBLOCKS, THREADS, SMEM_BYTES>>>(
        x, W1, b1, ln_g, ln_b, W2, b2, thr, adj_out, node_out);
}